// round 16
// baseline (speedup 1.0000x reference)
#include <cuda_runtime.h>
#include <cuda_fp16.h>
#include <cstdint>

#define NS    51
#define ROWS  64
#define TSEQ  2048
#define BATCH 8192
#define NCTA  (BATCH / ROWS)
#define NTH   256
#define KC1   4
#define KC2   7
#define ST1   72              // A1 row stride (halves) = 144B
#define ST2   120             // A2 row stride (halves) = 240B
#define XSTR  17
#define XSBUF 4352

#define A1SZ  9216
#define A2SZ  15360
#define OFF_A1   0            // single buffer
#define OFF_A2   9216         // double buffer -> end 39936
#define OFF_B1F  39936        // 26624 -> 66560
#define OFF_B2F  66560        // 46592 -> 113152
#define OFF_XS   113152       // 2*4352 -> 121856
#define OFF_YP   121856       // 16 slots * 64 rows * 8B = 8192 -> 130048
#define OFF_WL   130048       // 224
#define SMEM_BYTES 130304

__device__ __forceinline__ uint32_t smem_u32(const void* p) {
    uint32_t a;
    asm("{ .reg .u64 t; cvta.to.shared.u64 t, %1; cvt.u32.u64 %0, t; }" : "=r"(a) : "l"(p));
    return a;
}
__device__ __forceinline__ void sts16h(uint32_t a, float v) {
    unsigned short h = __half_as_ushort(__float2half_rn(v));
    asm volatile("st.shared.b16 [%0], %1;" :: "r"(a), "h"(h) : "memory");
}
__device__ __forceinline__ void sts32(uint32_t a, float v) {
    asm volatile("st.shared.b32 [%0], %1;" :: "r"(a), "f"(v) : "memory");
}
__device__ __forceinline__ void sts32u(uint32_t a, uint32_t v) {
    asm volatile("st.shared.b32 [%0], %1;" :: "r"(a), "r"(v) : "memory");
}
__device__ __forceinline__ float lds32(uint32_t a) {
    float v;
    asm volatile("ld.shared.b32 %0, [%1];" : "=f"(v) : "r"(a));
    return v;
}
__device__ __forceinline__ void lds64u(uint32_t& v0, uint32_t& v1, uint32_t a) {
    asm volatile("ld.shared.v2.b32 {%0,%1}, [%2];" : "=r"(v0), "=r"(v1) : "r"(a));
}
__device__ __forceinline__ void ldsm4(uint32_t* r, uint32_t a) {
    asm volatile("ldmatrix.sync.aligned.m8n8.x4.shared.b16 {%0,%1,%2,%3}, [%4];"
                 : "=r"(r[0]), "=r"(r[1]), "=r"(r[2]), "=r"(r[3]) : "r"(a));
}
__device__ __forceinline__ void hmma(float* d, const uint32_t* a, uint32_t b0, uint32_t b1) {
    asm volatile(
        "mma.sync.aligned.m16n8k16.row.col.f32.f16.f16.f32 "
        "{%0,%1,%2,%3}, {%4,%5,%6,%7}, {%8,%9}, {%0,%1,%2,%3};"
        : "+f"(d[0]), "+f"(d[1]), "+f"(d[2]), "+f"(d[3])
        : "r"(a[0]), "r"(a[1]), "r"(a[2]), "r"(a[3]), "r"(b0), "r"(b1));
}
__device__ __forceinline__ float ex2_(float x) {
    float r;
    asm("ex2.approx.ftz.f32 %0, %1;" : "=f"(r) : "f"(x));
    return r;
}
__device__ __forceinline__ float rcp_(float x) {
    float r;
    asm("rcp.approx.ftz.f32 %0, %1;" : "=f"(r) : "f"(x));
    return r;
}
// Merged LSTM cell: 5 ex2 + 2 rcp.
__device__ __forceinline__ float cell(float gi, float gf, float gg, float go, float& c) {
    const float L2E = 1.4426950408889634f;
    float a = ex2_(-L2E * gi);
    float b = ex2_(-2.f * L2E * gg);
    float u = ex2_(-L2E * gf);
    float pa = 1.f + a, pb = 1.f + b, pu = 1.f + u;
    float papb = pa * pb;
    float num = fmaf(1.f - b, pu, c * papb);
    c = num * rcp_(papb * pu);
    float o = ex2_(-L2E * go);
    float d2 = ex2_(-2.f * L2E * c);
    return (1.f - d2) * rcp_((1.f + o) * (1.f + d2));
}

// Weight element fetch by (unit, gate, k).
__device__ float w1val(int u, int g, int k, const float* Whh1, const float* Wih1,
                       const float* bih1, const float* bhh1) {
    if (u >= NS) return 0.f;
    int gu = g * NS + u;
    if (k < NS) return Whh1[gu * NS + k];
    if (k == 52) return Wih1[gu];
    if (k == 53) return bih1[gu] + bhh1[gu];
    return 0.f;
}
__device__ float w2val(int u, int g, int k, const float* Wih2, const float* Whh2,
                       const float* bih2, const float* bhh2) {
    if (u >= NS) return 0.f;
    int gu = g * NS + u;
    if (k < NS) return Wih2[gu * NS + k];
    if (k >= 52 && k - 52 < NS) return Whh2[gu * NS + (k - 52)];
    if (k == 104) return bih2[gu] + bhh2[gu];
    return 0.f;
}

extern __shared__ char smraw[];

__global__ __launch_bounds__(NTH, 1)
void lstm2_hmma_kernel(const float* __restrict__ x,
                       const float* __restrict__ Wih1, const float* __restrict__ Whh1,
                       const float* __restrict__ bih1, const float* __restrict__ bhh1,
                       const float* __restrict__ Wih2, const float* __restrict__ Whh2,
                       const float* __restrict__ bih2, const float* __restrict__ bhh2,
                       const float* __restrict__ Wlin, const float* __restrict__ blin,
                       float* __restrict__ out) {
    const uint32_t s0 = smem_u32(smraw);
    const int tid = threadIdx.x;
    const int wid = tid >> 5;
    const int lane = tid & 31;
    const long long rb = (long long)blockIdx.x * ROWS;

    // ---- one-time pack (R13 layouts) ----
    for (int i = tid; i < OFF_B1F / 4; i += NTH) sts32(s0 + i * 4, 0.f);
    for (int idx = tid; idx < 26 * KC1 * 64; idx += NTH) {
        int w = idx & 1, ln = (idx >> 1) & 31, kc = (idx >> 6) & 3, nt = idx >> 8;
        int c = ln >> 2;
        int u = (nt >> 1) * 4 + (c >> 1);
        int g = ((nt & 1) << 1) + (c & 1);
        int k = kc * 16 + (ln & 3) * 2 + w * 8;
        __half2 hv = __floats2half2_rn(w1val(u, g, k, Whh1, Wih1, bih1, bhh1),
                                       w1val(u, g, k + 1, Whh1, Wih1, bih1, bhh1));
        sts32u(s0 + OFF_B1F + idx * 4, *reinterpret_cast<uint32_t*>(&hv));
    }
    for (int idx = tid; idx < 26 * KC2 * 64; idx += NTH) {
        int w = idx & 1, ln = (idx >> 1) & 31;
        int r = idx >> 6;
        int kc = r % KC2, nt = r / KC2;
        int c = ln >> 2;
        int u = (nt >> 1) * 4 + (c >> 1);
        int g = ((nt & 1) << 1) + (c & 1);
        int k = kc * 16 + (ln & 3) * 2 + w * 8;
        __half2 hv = __floats2half2_rn(w2val(u, g, k, Wih2, Whh2, bih2, bhh2),
                                       w2val(u, g, k + 1, Wih2, Whh2, bih2, bhh2));
        sts32u(s0 + OFF_B2F + ((nt * KC2 + kc) * 64 + ln * 2 + w) * 4,
               *reinterpret_cast<uint32_t*>(&hv));
    }
    if (tid < ROWS) {
        sts16h(s0 + OFF_A1 + tid * (ST1 * 2) + 106, 1.f);
        sts16h(s0 + OFF_A2 + tid * (ST2 * 2) + 208, 1.f);
        sts16h(s0 + OFF_A2 + A2SZ + tid * (ST2 * 2) + 208, 1.f);
    }
    for (int u = tid; u < 56; u += NTH)
        sts32(s0 + OFF_WL + u * 4, (u < NS) ? Wlin[u] : 0.f);
    for (int idx = tid; idx < 1024; idx += NTH) {
        int row = idx >> 4, cc = idx & 15;
        float xv = x[(rb + row) * TSEQ + cc];
        sts32(s0 + OFF_XS + (row * XSTR + cc) * 4, xv);
        if (cc == 0) sts16h(s0 + OFF_A1 + row * (ST1 * 2) + 104, xv);
    }
    __syncthreads();

    // ---- mapping (R13) ----
    const int mt = wid & 3;
    const int nh = wid >> 2;
    const int np = 7 - nh;
    const int tile0 = nh * 14;
    const int ptid = nh * 32 + lane;
    const int barid = mt + 1;
    const int q = lane & 3;
    const float bl = blin[0];

    const int rE0 = mt * 16 + (lane >> 2);
    const int u0 = nh * 28 + q;
    const int lrow0 = mt * 16 + (lane & 15);
    const uint32_t khalf = ((lane >> 4) & 1) * 16;
    const uint32_t a1m = s0 + OFF_A1 + lrow0 * (ST1 * 2) + khalf;
    const uint32_t a2m = s0 + OFF_A2 + lrow0 * (ST2 * 2) + khalf;
    const uint32_t b1p = s0 + OFF_B1F + tile0 * 1024 + lane * 8;
    const uint32_t b2p = s0 + OFF_B2F + tile0 * 1792 + lane * 8;
    const uint32_t hA1_0 = s0 + OFF_A1 + rE0 * (ST1 * 2) + u0 * 2;
    const uint32_t hA1_1 = hA1_0 + 8 * (ST1 * 2);
    const uint32_t hA2_0 = s0 + OFF_A2 + rE0 * (ST2 * 2) + u0 * 2;
    const uint32_t hA2_1 = hA2_0 + 8 * (ST2 * 2);
    const uint32_t ypw0 = s0 + OFF_YP + rE0 * 8 + nh * 4;

    float wl[7];
#pragma unroll
    for (int p = 0; p < 7; p++)
        wl[p] = (p < np) ? lds32(s0 + OFF_WL + (u0 + 4 * p) * 4) : 0.f;

    float c1a[7], c1b[7], c2a[7], c2b[7];
    float d2r[7][2][4];
    float h1r[2][2];            // epi1-compute(pairs 0,1) results carried I -> II
    float ypB0 = 0.f, ypB1 = 0.f;   // epi2 partials (pairs 0..2) from phase III
#pragma unroll
    for (int i = 0; i < 7; i++) { c1a[i] = c1b[i] = c2a[i] = c2b[i] = 0.f; }

#define PBAR() asm volatile("bar.sync %0, 64;" :: "r"(barid) : "memory")

    for (int t = 0; t < TSEQ; t++) {
        const int tc = t & 15;
        const uint32_t bA2 = (uint32_t)(t & 1) * A2SZ;

        // ======== phase I: gemm1(t) ⊕ epi2(t-1).pairs3+ ⊕ epi1(t).pairs0-1 ========
        uint32_t af[4][4];
        float d1[7][2][4];
#pragma unroll
        for (int kc = 0; kc < 4; kc++) ldsm4(af[kc], a1m + kc * 32);
        {
            float ypA0 = 0.f, ypA1 = 0.f;
#pragma unroll
            for (int p = 0; p < 7; p++) if (p < np) {
#pragma unroll
                for (int tt = 0; tt < 2; tt++) {
                    float* dd = d1[p][tt];
                    dd[0] = dd[1] = dd[2] = dd[3] = 0.f;
                    uint32_t b0, b1;
#pragma unroll
                    for (int kc = 0; kc < 4; kc++) {
                        lds64u(b0, b1, b1p + (((2 * p + tt) * 4 + kc) << 8));
                        hmma(dd, af[kc], b0, b1);
                    }
                }
                if (p >= 3 && t) {   // epi2(t-1) for pairs 3..np-1
                    float h0 = cell(d2r[p][0][0], d2r[p][0][1], d2r[p][1][0], d2r[p][1][1], c2a[p]);
                    float h1 = cell(d2r[p][0][2], d2r[p][0][3], d2r[p][1][2], d2r[p][1][3], c2b[p]);
                    sts16h(hA2_0 + bA2 + 104 + 8 * p, h0);
                    sts16h(hA2_1 + bA2 + 104 + 8 * p, h1);
                    ypA0 = fmaf(h0, wl[p], ypA0);
                    ypA1 = fmaf(h1, wl[p], ypA1);
                }
            }
            // epi1-compute(t) for pairs 0,1 (stores deferred past BAR1)
#pragma unroll
            for (int p = 0; p < 2; p++) {
                h1r[p][0] = cell(d1[p][0][0], d1[p][0][1], d1[p][1][0], d1[p][1][1], c1a[p]);
                h1r[p][1] = cell(d1[p][0][2], d1[p][0][3], d1[p][1][2], d1[p][1][3], c1b[p]);
            }
            if (t) {   // finalize y(t-1) = ypA + ypB
                float yp0 = ypA0 + ypB0, yp1 = ypA1 + ypB1;
                yp0 += __shfl_xor_sync(0xffffffffu, yp0, 1);
                yp0 += __shfl_xor_sync(0xffffffffu, yp0, 2);
                yp1 += __shfl_xor_sync(0xffffffffu, yp1, 1);
                yp1 += __shfl_xor_sync(0xffffffffu, yp1, 2);
                if (q == 0) {
                    uint32_t so = (uint32_t)((t - 1) & 15) * 512;
                    sts32(ypw0 + so, yp0);
                    sts32(ypw0 + 64 + so, yp1);
                }
            }
        }

        PBAR();   // BAR_1

        // deferred epi1 stores for pairs 0,1
#pragma unroll
        for (int p = 0; p < 2; p++) {
            sts16h(hA1_0 + 8 * p, h1r[p][0]);
            sts16h(hA1_1 + 8 * p, h1r[p][1]);
            sts16h(hA2_0 + bA2 + 8 * p, h1r[p][0]);
            sts16h(hA2_1 + bA2 + 8 * p, h1r[p][1]);
        }

        if (tc == 0) {
            if (t) {
                for (int idx = ptid; idx < 256; idx += 64) {
                    int rl = idx >> 4, cc = idx & 15, row = mt * 16 + rl;
                    uint32_t ypb = s0 + OFF_YP + (uint32_t)cc * 512 + row * 8;
                    out[(rb + row) * TSEQ + (t - 16) + cc] =
                        lds32(ypb) + lds32(ypb + 4) + bl;
                }
            }
            if (t + 16 < TSEQ) {
                uint32_t xb = s0 + OFF_XS + (uint32_t)(((t >> 4) + 1) & 1) * XSBUF;
                for (int idx = ptid; idx < 256; idx += 64) {
                    int rl = idx >> 4, cc = idx & 15, row = mt * 16 + rl;
                    sts32(xb + (row * XSTR + cc) * 4, x[(rb + row) * TSEQ + t + 16 + cc]);
                }
            }
        }

        // ======== phase II: epi1(t).pairs2+ ⊕ gemm2(t).kc4-6 ========
        uint32_t af2[3][4];
#pragma unroll
        for (int kc = 0; kc < 3; kc++) ldsm4(af2[kc], a2m + bA2 + (4 + kc) * 32);
#pragma unroll
        for (int p = 0; p < 7; p++) if (p < np) {
            if (p >= 2) {
                float h0 = cell(d1[p][0][0], d1[p][0][1], d1[p][1][0], d1[p][1][1], c1a[p]);
                float h1 = cell(d1[p][0][2], d1[p][0][3], d1[p][1][2], d1[p][1][3], c1b[p]);
                sts16h(hA1_0 + 8 * p, h0);
                sts16h(hA1_1 + 8 * p, h1);
                sts16h(hA2_0 + bA2 + 8 * p, h0);
                sts16h(hA2_1 + bA2 + 8 * p, h1);
            }
#pragma unroll
            for (int tt = 0; tt < 2; tt++) {
                float* dd = d2r[p][tt];
                dd[0] = dd[1] = dd[2] = dd[3] = 0.f;
                uint32_t b0, b1;
#pragma unroll
                for (int kc = 0; kc < 3; kc++) {
                    lds64u(b0, b1, b2p + (((2 * p + tt) * 7 + 4 + kc) << 8));
                    hmma(dd, af2[kc], b0, b1);
                }
            }
        }
        if (ptid < 16 && t + 1 < TSEQ) {
            int row = mt * 16 + ptid;
            uint32_t xb = s0 + OFF_XS + (uint32_t)(((t + 1) >> 4) & 1) * XSBUF;
            sts16h(s0 + OFF_A1 + row * (ST1 * 2) + 104,
                   lds32(xb + (row * XSTR + ((t + 1) & 15)) * 4));
        }

        PBAR();   // BAR_2

        // ======== phase III: gemm2(t).kc0-3 ⊕ epi2(t).pairs0-2 ========
        const uint32_t nA2 = A2SZ - bA2;   // A2[b(t+1)]
        ypB0 = 0.f; ypB1 = 0.f;
#pragma unroll
        for (int kc = 0; kc < 4; kc++) ldsm4(af[kc], a2m + bA2 + kc * 32);
#pragma unroll
        for (int p = 0; p < 7; p++) if (p < np) {
#pragma unroll
            for (int tt = 0; tt < 2; tt++) {
                uint32_t b0, b1;
#pragma unroll
                for (int kc = 0; kc < 4; kc++) {
                    lds64u(b0, b1, b2p + (((2 * p + tt) * 7 + kc) << 8));
                    hmma(d2r[p][tt], af[kc], b0, b1);
                }
            }
            if (p < 3) {   // epi2(t) now; h2 -> A2[b(t+1)]
                float h0 = cell(d2r[p][0][0], d2r[p][0][1], d2r[p][1][0], d2r[p][1][1], c2a[p]);
                float h1 = cell(d2r[p][0][2], d2r[p][0][3], d2r[p][1][2], d2r[p][1][3], c2b[p]);
                sts16h(hA2_0 + nA2 + 104 + 8 * p, h0);
                sts16h(hA2_1 + nA2 + 104 + 8 * p, h1);
                ypB0 = fmaf(h0, wl[p], ypB0);
                ypB1 = fmaf(h1, wl[p], ypB1);
            }
        }
    }

    // ---- epilogue: epi2(T-1).pairs3+ + final chunk flush ----
    {
        float yp0 = ypB0, yp1 = ypB1;
#pragma unroll
        for (int p = 3; p < 7; p++) if (p < np) {
            float h0 = cell(d2r[p][0][0], d2r[p][0][1], d2r[p][1][0], d2r[p][1][1], c2a[p]);
            float h1 = cell(d2r[p][0][2], d2r[p][0][3], d2r[p][1][2], d2r[p][1][3], c2b[p]);
            yp0 = fmaf(h0, wl[p], yp0);
            yp1 = fmaf(h1, wl[p], yp1);
        }
        yp0 += __shfl_xor_sync(0xffffffffu, yp0, 1);
        yp0 += __shfl_xor_sync(0xffffffffu, yp0, 2);
        yp1 += __shfl_xor_sync(0xffffffffu, yp1, 1);
        yp1 += __shfl_xor_sync(0xffffffffu, yp1, 2);
        if (q == 0) {
            sts32(ypw0 + 15u * 512, yp0);
            sts32(ypw0 + 64 + 15u * 512, yp1);
        }
    }
    PBAR();
    for (int idx = ptid; idx < 256; idx += 64) {
        int rl = idx >> 4, cc = idx & 15, row = mt * 16 + rl;
        uint32_t ypb = s0 + OFF_YP + (uint32_t)cc * 512 + row * 8;
        out[(rb + row) * TSEQ + (TSEQ - 16) + cc] = lds32(ypb) + lds32(ypb + 4) + bl;
    }
#undef PBAR
}

extern "C" void kernel_launch(void* const* d_in, const int* in_sizes, int n_in,
                              void* d_out, int out_size) {
    const float* x    = (const float*)d_in[0];
    const float* Wih1 = (const float*)d_in[1];
    const float* Whh1 = (const float*)d_in[2];
    const float* bih1 = (const float*)d_in[3];
    const float* bhh1 = (const float*)d_in[4];
    const float* Wih2 = (const float*)d_in[5];
    const float* Whh2 = (const float*)d_in[6];
    const float* bih2 = (const float*)d_in[7];
    const float* bhh2 = (const float*)d_in[8];
    const float* Wlin = (const float*)d_in[9];
    const float* blin = (const float*)d_in[10];

    cudaFuncSetAttribute(lstm2_hmma_kernel,
                         cudaFuncAttributeMaxDynamicSharedMemorySize, SMEM_BYTES);
    lstm2_hmma_kernel<<<NCTA, NTH, SMEM_BYTES>>>(
        x, Wih1, Whh1, bih1, bhh1, Wih2, Whh2, bih2, bhh2, Wlin, blin,
        (float*)d_out);
}

// round 17
// speedup vs baseline: 1.1708x; 1.1708x over previous
#include <cuda_runtime.h>
#include <cuda_fp16.h>
#include <cstdint>

#define NS    51
#define ROWS  64
#define TSEQ  2048
#define BATCH 8192
#define NCTA  (BATCH / ROWS)
#define NTH   256
#define KC1   4
#define KC2   7
#define ST1   72              // A1 row stride (halves) = 144B
#define ST2   120             // A2 row stride (halves) = 240B
#define XSTR  17
#define XSBUF 4352

#define A1SZ  9216
#define A2SZ  15360
#define OFF_A1   0            // single buffer
#define OFF_A2   9216         // double buffer -> end 39936
#define OFF_B1F  39936        // 26624 -> 66560
#define OFF_B2F  66560        // 46592 -> 113152
#define OFF_XS   113152       // 2*4352 -> 121856
#define OFF_YP   121856       // 16 slots * 64 rows * 8B = 8192 -> 130048
#define OFF_WL   130048       // 224
#define SMEM_BYTES 130304

__device__ __forceinline__ uint32_t smem_u32(const void* p) {
    uint32_t a;
    asm("{ .reg .u64 t; cvta.to.shared.u64 t, %1; cvt.u32.u64 %0, t; }" : "=r"(a) : "l"(p));
    return a;
}
__device__ __forceinline__ void sts16h(uint32_t a, float v) {
    unsigned short h = __half_as_ushort(__float2half_rn(v));
    asm volatile("st.shared.b16 [%0], %1;" :: "r"(a), "h"(h) : "memory");
}
__device__ __forceinline__ void sts32(uint32_t a, float v) {
    asm volatile("st.shared.b32 [%0], %1;" :: "r"(a), "f"(v) : "memory");
}
__device__ __forceinline__ void sts32u(uint32_t a, uint32_t v) {
    asm volatile("st.shared.b32 [%0], %1;" :: "r"(a), "r"(v) : "memory");
}
__device__ __forceinline__ float lds32(uint32_t a) {
    float v;
    asm volatile("ld.shared.b32 %0, [%1];" : "=f"(v) : "r"(a));
    return v;
}
__device__ __forceinline__ void lds64u(uint32_t& v0, uint32_t& v1, uint32_t a) {
    asm volatile("ld.shared.v2.b32 {%0,%1}, [%2];" : "=r"(v0), "=r"(v1) : "r"(a));
}
__device__ __forceinline__ void ldsm4(uint32_t* r, uint32_t a) {
    asm volatile("ldmatrix.sync.aligned.m8n8.x4.shared.b16 {%0,%1,%2,%3}, [%4];"
                 : "=r"(r[0]), "=r"(r[1]), "=r"(r[2]), "=r"(r[3]) : "r"(a));
}
__device__ __forceinline__ void hmma(float* d, const uint32_t* a, uint32_t b0, uint32_t b1) {
    asm volatile(
        "mma.sync.aligned.m16n8k16.row.col.f32.f16.f16.f32 "
        "{%0,%1,%2,%3}, {%4,%5,%6,%7}, {%8,%9}, {%0,%1,%2,%3};"
        : "+f"(d[0]), "+f"(d[1]), "+f"(d[2]), "+f"(d[3])
        : "r"(a[0]), "r"(a[1]), "r"(a[2]), "r"(a[3]), "r"(b0), "r"(b1));
}
__device__ __forceinline__ float tanh_(float x) {
    float r;
    asm("tanh.approx.f32 %0, %1;" : "=f"(r) : "f"(x));
    return r;
}
// LSTM cell via HW tanh: 5 MUFU (was 7 with ex2/rcp form).
__device__ __forceinline__ float cell(float gi, float gf, float gg, float go, float& c) {
    float si = fmaf(0.5f, tanh_(0.5f * gi), 0.5f);
    float sf = fmaf(0.5f, tanh_(0.5f * gf), 0.5f);
    float so = fmaf(0.5f, tanh_(0.5f * go), 0.5f);
    float tg = tanh_(gg);
    c = fmaf(sf, c, si * tg);
    return so * tanh_(c);
}

// Weight element fetch by (unit, gate, k).
__device__ float w1val(int u, int g, int k, const float* Whh1, const float* Wih1,
                       const float* bih1, const float* bhh1) {
    if (u >= NS) return 0.f;
    int gu = g * NS + u;
    if (k < NS) return Whh1[gu * NS + k];
    if (k == 52) return Wih1[gu];
    if (k == 53) return bih1[gu] + bhh1[gu];
    return 0.f;
}
__device__ float w2val(int u, int g, int k, const float* Wih2, const float* Whh2,
                       const float* bih2, const float* bhh2) {
    if (u >= NS) return 0.f;
    int gu = g * NS + u;
    if (k < NS) return Wih2[gu * NS + k];
    if (k >= 52 && k - 52 < NS) return Whh2[gu * NS + (k - 52)];
    if (k == 104) return bih2[gu] + bhh2[gu];
    return 0.f;
}

extern __shared__ char smraw[];

__global__ __launch_bounds__(NTH, 1)
void lstm2_hmma_kernel(const float* __restrict__ x,
                       const float* __restrict__ Wih1, const float* __restrict__ Whh1,
                       const float* __restrict__ bih1, const float* __restrict__ bhh1,
                       const float* __restrict__ Wih2, const float* __restrict__ Whh2,
                       const float* __restrict__ bih2, const float* __restrict__ bhh2,
                       const float* __restrict__ Wlin, const float* __restrict__ blin,
                       float* __restrict__ out) {
    const uint32_t s0 = smem_u32(smraw);
    const int tid = threadIdx.x;
    const int wid = tid >> 5;
    const int lane = tid & 31;
    const long long rb = (long long)blockIdx.x * ROWS;

    // ---- one-time pack (R13 layouts) ----
    for (int i = tid; i < OFF_B1F / 4; i += NTH) sts32(s0 + i * 4, 0.f);
    // Column map: tile nt, col c -> unit (nt>>1)*4 + (c>>1), gate (nt&1)*2 + (c&1)
    for (int idx = tid; idx < 26 * KC1 * 64; idx += NTH) {
        int w = idx & 1, ln = (idx >> 1) & 31, kc = (idx >> 6) & 3, nt = idx >> 8;
        int c = ln >> 2;
        int u = (nt >> 1) * 4 + (c >> 1);
        int g = ((nt & 1) << 1) + (c & 1);
        int k = kc * 16 + (ln & 3) * 2 + w * 8;
        __half2 hv = __floats2half2_rn(w1val(u, g, k, Whh1, Wih1, bih1, bhh1),
                                       w1val(u, g, k + 1, Whh1, Wih1, bih1, bhh1));
        sts32u(s0 + OFF_B1F + idx * 4, *reinterpret_cast<uint32_t*>(&hv));
    }
    for (int idx = tid; idx < 26 * KC2 * 64; idx += NTH) {
        int w = idx & 1, ln = (idx >> 1) & 31;
        int r = idx >> 6;
        int kc = r % KC2, nt = r / KC2;
        int c = ln >> 2;
        int u = (nt >> 1) * 4 + (c >> 1);
        int g = ((nt & 1) << 1) + (c & 1);
        int k = kc * 16 + (ln & 3) * 2 + w * 8;
        __half2 hv = __floats2half2_rn(w2val(u, g, k, Wih2, Whh2, bih2, bhh2),
                                       w2val(u, g, k + 1, Wih2, Whh2, bih2, bhh2));
        sts32u(s0 + OFF_B2F + ((nt * KC2 + kc) * 64 + ln * 2 + w) * 4,
               *reinterpret_cast<uint32_t*>(&hv));
    }
    if (tid < ROWS) {
        sts16h(s0 + OFF_A1 + tid * (ST1 * 2) + 106, 1.f);
        sts16h(s0 + OFF_A2 + tid * (ST2 * 2) + 208, 1.f);
        sts16h(s0 + OFF_A2 + A2SZ + tid * (ST2 * 2) + 208, 1.f);
    }
    for (int u = tid; u < 56; u += NTH)
        sts32(s0 + OFF_WL + u * 4, (u < NS) ? Wlin[u] : 0.f);
    for (int idx = tid; idx < 1024; idx += NTH) {
        int row = idx >> 4, cc = idx & 15;
        float xv = x[(rb + row) * TSEQ + cc];
        sts32(s0 + OFF_XS + (row * XSTR + cc) * 4, xv);
        if (cc == 0) sts16h(s0 + OFF_A1 + row * (ST1 * 2) + 104, xv);
    }
    __syncthreads();

    // ---- mapping (R13) ----
    const int mt = wid & 3;
    const int nh = wid >> 2;
    const int np = 7 - nh;
    const int tile0 = nh * 14;
    const int ptid = nh * 32 + lane;
    const int barid = mt + 1;
    const int q = lane & 3;
    const float bl = blin[0];

    const int rE0 = mt * 16 + (lane >> 2);
    const int u0 = nh * 28 + q;
    const int lrow0 = mt * 16 + (lane & 15);
    const uint32_t khalf = ((lane >> 4) & 1) * 16;
    const uint32_t a1m = s0 + OFF_A1 + lrow0 * (ST1 * 2) + khalf;
    const uint32_t a2m = s0 + OFF_A2 + lrow0 * (ST2 * 2) + khalf;
    const uint32_t b1p = s0 + OFF_B1F + tile0 * 1024 + lane * 8;
    const uint32_t b2p = s0 + OFF_B2F + tile0 * 1792 + lane * 8;
    const uint32_t hA1_0 = s0 + OFF_A1 + rE0 * (ST1 * 2) + u0 * 2;
    const uint32_t hA1_1 = hA1_0 + 8 * (ST1 * 2);
    const uint32_t hA2_0 = s0 + OFF_A2 + rE0 * (ST2 * 2) + u0 * 2;
    const uint32_t hA2_1 = hA2_0 + 8 * (ST2 * 2);
    const uint32_t ypw0 = s0 + OFF_YP + rE0 * 8 + nh * 4;

    float wl[7];
#pragma unroll
    for (int p = 0; p < 7; p++)
        wl[p] = (p < np) ? lds32(s0 + OFF_WL + (u0 + 4 * p) * 4) : 0.f;

    float c1a[7], c1b[7], c2a[7], c2b[7];
    float d2r[7][2][4];
#pragma unroll
    for (int i = 0; i < 7; i++) { c1a[i] = c1b[i] = c2a[i] = c2b[i] = 0.f; }

#define PBAR() asm volatile("bar.sync %0, 64;" :: "r"(barid) : "memory")

    for (int t = 0; t < TSEQ; t++) {
        const int tc = t & 15;
        const uint32_t bA2 = (uint32_t)(t & 1) * A2SZ;

        // ======== phase I: gemm1(t) ⊕ epi2(t-1) ========
        uint32_t af[4][4];
        float d1[7][2][4];
#pragma unroll
        for (int kc = 0; kc < 4; kc++) ldsm4(af[kc], a1m + kc * 32);
        if (t) {
            float yp0 = 0.f, yp1 = 0.f;
#pragma unroll
            for (int p = 0; p < 7; p++) if (p < np) {
#pragma unroll
                for (int tt = 0; tt < 2; tt++) {
                    float* dd = d1[p][tt];
                    dd[0] = dd[1] = dd[2] = dd[3] = 0.f;
                    uint32_t b0, b1;
#pragma unroll
                    for (int kc = 0; kc < 4; kc++) {
                        lds64u(b0, b1, b1p + (((2 * p + tt) * 4 + kc) << 8));
                        hmma(dd, af[kc], b0, b1);
                    }
                }
                float h0 = cell(d2r[p][0][0], d2r[p][0][1], d2r[p][1][0], d2r[p][1][1], c2a[p]);
                float h1 = cell(d2r[p][0][2], d2r[p][0][3], d2r[p][1][2], d2r[p][1][3], c2b[p]);
                sts16h(hA2_0 + bA2 + 104 + 8 * p, h0);   // h2(t-1) -> A2[b(t)]
                sts16h(hA2_1 + bA2 + 104 + 8 * p, h1);
                yp0 = fmaf(h0, wl[p], yp0);
                yp1 = fmaf(h1, wl[p], yp1);
            }
            yp0 += __shfl_xor_sync(0xffffffffu, yp0, 1);
            yp0 += __shfl_xor_sync(0xffffffffu, yp0, 2);
            yp1 += __shfl_xor_sync(0xffffffffu, yp1, 1);
            yp1 += __shfl_xor_sync(0xffffffffu, yp1, 2);
            if (q == 0) {
                uint32_t so = (uint32_t)((t - 1) & 15) * 512;
                sts32(ypw0 + so, yp0);
                sts32(ypw0 + 64 + so, yp1);
            }
        } else {
#pragma unroll
            for (int p = 0; p < 7; p++) if (p < np) {
#pragma unroll
                for (int tt = 0; tt < 2; tt++) {
                    float* dd = d1[p][tt];
                    dd[0] = dd[1] = dd[2] = dd[3] = 0.f;
                    uint32_t b0, b1;
#pragma unroll
                    for (int kc = 0; kc < 4; kc++) {
                        lds64u(b0, b1, b1p + (((2 * p + tt) * 4 + kc) << 8));
                        hmma(dd, af[kc], b0, b1);
                    }
                }
            }
        }

        PBAR();   // BAR_1

        if (tc == 0) {
            if (t) {
                for (int idx = ptid; idx < 256; idx += 64) {
                    int rl = idx >> 4, cc = idx & 15, row = mt * 16 + rl;
                    uint32_t ypb = s0 + OFF_YP + (uint32_t)cc * 512 + row * 8;
                    out[(rb + row) * TSEQ + (t - 16) + cc] =
                        lds32(ypb) + lds32(ypb + 4) + bl;
                }
            }
            if (t + 16 < TSEQ) {
                uint32_t xb = s0 + OFF_XS + (uint32_t)(((t >> 4) + 1) & 1) * XSBUF;
                for (int idx = ptid; idx < 256; idx += 64) {
                    int rl = idx >> 4, cc = idx & 15, row = mt * 16 + rl;
                    sts32(xb + (row * XSTR + cc) * 4, x[(rb + row) * TSEQ + t + 16 + cc]);
                }
            }
        }

        // ======== phase II: epi1(t) ⊕ gemm2(t).kc4-6 ========
        uint32_t af2[3][4];
#pragma unroll
        for (int kc = 0; kc < 3; kc++) ldsm4(af2[kc], a2m + bA2 + (4 + kc) * 32);
#pragma unroll
        for (int p = 0; p < 7; p++) if (p < np) {
            float h0 = cell(d1[p][0][0], d1[p][0][1], d1[p][1][0], d1[p][1][1], c1a[p]);
            float h1 = cell(d1[p][0][2], d1[p][0][3], d1[p][1][2], d1[p][1][3], c1b[p]);
            sts16h(hA1_0 + 8 * p, h0);              // h1(t) -> A1 (gemm1(t+1))
            sts16h(hA1_1 + 8 * p, h1);
            sts16h(hA2_0 + bA2 + 8 * p, h0);        // h1(t) -> A2[b(t)] (kc0-3)
            sts16h(hA2_1 + bA2 + 8 * p, h1);
#pragma unroll
            for (int tt = 0; tt < 2; tt++) {
                float* dd = d2r[p][tt];
                dd[0] = dd[1] = dd[2] = dd[3] = 0.f;
                uint32_t b0, b1;
#pragma unroll
                for (int kc = 0; kc < 3; kc++) {
                    lds64u(b0, b1, b2p + (((2 * p + tt) * 7 + 4 + kc) << 8));
                    hmma(dd, af2[kc], b0, b1);
                }
            }
        }
        if (ptid < 16 && t + 1 < TSEQ) {          // x(t+1) -> A1 col 52
            int row = mt * 16 + ptid;
            uint32_t xb = s0 + OFF_XS + (uint32_t)(((t + 1) >> 4) & 1) * XSBUF;
            sts16h(s0 + OFF_A1 + row * (ST1 * 2) + 104,
                   lds32(xb + (row * XSTR + ((t + 1) & 15)) * 4));
        }

        PBAR();   // BAR_2

        // ======== phase III: gemm2(t).kc0-3 (carried into next phase I) ========
#pragma unroll
        for (int kc = 0; kc < 4; kc++) ldsm4(af[kc], a2m + bA2 + kc * 32);
#pragma unroll
        for (int p = 0; p < 7; p++) if (p < np) {
#pragma unroll
            for (int tt = 0; tt < 2; tt++) {
                uint32_t b0, b1;
#pragma unroll
                for (int kc = 0; kc < 4; kc++) {
                    lds64u(b0, b1, b2p + (((2 * p + tt) * 7 + kc) << 8));
                    hmma(d2r[p][tt], af[kc], b0, b1);
                }
            }
        }
    }

    // ---- epilogue: epi2(T-1) + final chunk flush ----
    {
        float yp0 = 0.f, yp1 = 0.f;
#pragma unroll
        for (int p = 0; p < 7; p++) if (p < np) {
            float h0 = cell(d2r[p][0][0], d2r[p][0][1], d2r[p][1][0], d2r[p][1][1], c2a[p]);
            float h1 = cell(d2r[p][0][2], d2r[p][0][3], d2r[p][1][2], d2r[p][1][3], c2b[p]);
            yp0 = fmaf(h0, wl[p], yp0);
            yp1 = fmaf(h1, wl[p], yp1);
        }
        yp0 += __shfl_xor_sync(0xffffffffu, yp0, 1);
        yp0 += __shfl_xor_sync(0xffffffffu, yp0, 2);
        yp1 += __shfl_xor_sync(0xffffffffu, yp1, 1);
        yp1 += __shfl_xor_sync(0xffffffffu, yp1, 2);
        if (q == 0) {
            sts32(ypw0 + 15u * 512, yp0);
            sts32(ypw0 + 64 + 15u * 512, yp1);
        }
    }
    PBAR();
    for (int idx = ptid; idx < 256; idx += 64) {
        int rl = idx >> 4, cc = idx & 15, row = mt * 16 + rl;
        uint32_t ypb = s0 + OFF_YP + (uint32_t)cc * 512 + row * 8;
        out[(rb + row) * TSEQ + (TSEQ - 16) + cc] = lds32(ypb) + lds32(ypb + 4) + bl;
    }
#undef PBAR
}

extern "C" void kernel_launch(void* const* d_in, const int* in_sizes, int n_in,
                              void* d_out, int out_size) {
    const float* x    = (const float*)d_in[0];
    const float* Wih1 = (const float*)d_in[1];
    const float* Whh1 = (const float*)d_in[2];
    const float* bih1 = (const float*)d_in[3];
    const float* bhh1 = (const float*)d_in[4];
    const float* Wih2 = (const float*)d_in[5];
    const float* Whh2 = (const float*)d_in[6];
    const float* bih2 = (const float*)d_in[7];
    const float* bhh2 = (const float*)d_in[8];
    const float* Wlin = (const float*)d_in[9];
    const float* blin = (const float*)d_in[10];

    cudaFuncSetAttribute(lstm2_hmma_kernel,
                         cudaFuncAttributeMaxDynamicSharedMemorySize, SMEM_BYTES);
    lstm2_hmma_kernel<<<NCTA, NTH, SMEM_BYTES>>>(
        x, Wih1, Whh1, bih1, bhh1, Wih2, Whh2, bih2, bhh2, Wlin, blin,
        (float*)d_out);
}